// round 2
// baseline (speedup 1.0000x reference)
#include <cuda_runtime.h>
#include <cstdint>

// x[32768,2048] fp32, bank[20,2048] fp32 -> out[32768,2048] fp32
constexpr int FEA      = 2048;
constexpr int NBANK    = 20;
constexpr int RPW      = 2;               // rows per warp
constexpr int NWARP    = 16;
constexpr int RPB      = RPW * NWARP;     // 32 rows per CTA
constexpr int NTHREADS = 512;
constexpr int KC       = 128;             // k-cols per chunk (32 lanes * 4 floats)
constexpr int NCHUNK   = FEA / KC;        // 16
constexpr float LAMBDA = 0.0025f;
constexpr int SMEM_BYTES = NBANK * FEA * (int)sizeof(float);  // 163840

typedef unsigned long long u64;   // packed f32x2: lo = float0, hi = float1

__device__ __forceinline__ u64 ffma2(u64 a, u64 b, u64 c) {
    u64 d;
    asm("fma.rn.f32x2 %0, %1, %2, %3;" : "=l"(d) : "l"(a), "l"(b), "l"(c));
    return d;
}
__device__ __forceinline__ u64 pack2(float lo, float hi) {
    u64 d;
    asm("mov.b64 %0, {%1, %2};" : "=l"(d) : "f"(lo), "f"(hi));
    return d;
}
__device__ __forceinline__ void unpack2(u64 v, float& lo, float& hi) {
    asm("mov.b64 {%0, %1}, %2;" : "=f"(lo), "=f"(hi) : "l"(v));
}
__device__ __forceinline__ float tanh_fast(float v) {
    float r;
    asm("tanh.approx.f32 %0, %1;" : "=f"(r) : "f"(v));
    return r;
}

extern __shared__ float s_bank[];  // [NBANK][FEA]

__global__ __launch_bounds__(NTHREADS, 1)
void memunit_fused(const float* __restrict__ x,
                   const float* __restrict__ bank,
                   float* __restrict__ out,
                   int n_tiles)
{
    const int tid = threadIdx.x;

    // bank -> SMEM once per persistent CTA (coalesced 16B)
    for (int i = tid; i < NBANK * FEA / 4; i += NTHREADS)
        reinterpret_cast<float4*>(s_bank)[i] =
            reinterpret_cast<const float4*>(bank)[i];
    __syncthreads();

    const int warp = tid >> 5;
    const int lane = tid & 31;

    for (int tile = blockIdx.x; tile < n_tiles; tile += gridDim.x) {
        const long row0 = (long)tile * RPB + warp * RPW;
        const float* xp = x + row0 * FEA + lane * 4;

        // acc[r][j]: packed f32x2 partial dot products.
        // .lo accumulates k-elems {0,2} of this lane's float4, .hi elems {1,3}.
        u64 acc[RPW][NBANK];
        #pragma unroll
        for (int r = 0; r < RPW; r++)
            #pragma unroll
            for (int j = 0; j < NBANK; j++) acc[r][j] = 0ull;

        // software-pipelined x prefetch (2 x LDG.128 in flight per warp)
        ulonglong2 xv[RPW];
        #pragma unroll
        for (int r = 0; r < RPW; r++)
            xv[r] = *reinterpret_cast<const ulonglong2*>(xp + r * FEA);

        #pragma unroll 1
        for (int kc = 0; kc < NCHUNK; kc++) {
            ulonglong2 cur[RPW];
            #pragma unroll
            for (int r = 0; r < RPW; r++) cur[r] = xv[r];

            const int nk = (kc + 1) & (NCHUNK - 1);   // wrap: harmless re-read at end
            #pragma unroll
            for (int r = 0; r < RPW; r++)
                xv[r] = *reinterpret_cast<const ulonglong2*>(xp + r * FEA + nk * KC);

            const int kb = kc * KC + lane * 4;
            #pragma unroll
            for (int j = 0; j < NBANK; j++) {
                const ulonglong2 b =
                    *reinterpret_cast<const ulonglong2*>(&s_bank[j * FEA + kb]);
                #pragma unroll
                for (int r = 0; r < RPW; r++) {
                    acc[r][j] = ffma2(cur[r].x, b.x, acc[r][j]);
                    acc[r][j] = ffma2(cur[r].y, b.y, acc[r][j]);
                }
            }
        }

        // ---- collapse packed halves + butterfly reduce across 32 lanes --------
        float att[RPW][NBANK];
        #pragma unroll
        for (int r = 0; r < RPW; r++)
            #pragma unroll
            for (int j = 0; j < NBANK; j++) {
                float lo, hi;
                unpack2(acc[r][j], lo, hi);
                float v = lo + hi;
                v += __shfl_xor_sync(0xffffffffu, v, 16);
                v += __shfl_xor_sync(0xffffffffu, v, 8);
                v += __shfl_xor_sync(0xffffffffu, v, 4);
                v += __shfl_xor_sync(0xffffffffu, v, 2);
                v += __shfl_xor_sync(0xffffffffu, v, 1);
                att[r][j] = v;
            }

        // ---- softmax -> softshrink -> softmax (per row, redundant per lane) ---
        #pragma unroll
        for (int r = 0; r < RPW; r++) {
            float m = att[r][0];
            #pragma unroll
            for (int j = 1; j < NBANK; j++) m = fmaxf(m, att[r][j]);

            float s = 0.f;
            #pragma unroll
            for (int j = 0; j < NBANK; j++) {
                const float e = __expf(att[r][j] - m);
                att[r][j] = e;
                s += e;
            }
            const float inv = 1.0f / s;

            float m2 = 0.f;   // att >= 0 => softshrink = max(att - lambda, 0)
            #pragma unroll
            for (int j = 0; j < NBANK; j++) {
                float a = fmaxf(att[r][j] * inv - LAMBDA, 0.f);
                att[r][j] = a;
                m2 = fmaxf(m2, a);
            }

            float s2 = 0.f;
            #pragma unroll
            for (int j = 0; j < NBANK; j++) {
                const float e = __expf(att[r][j] - m2);
                att[r][j] = e;
                s2 += e;
            }
            const float inv2 = 1.0f / s2;
            // broadcast-pack final att into the acc registers (reuse, no growth)
            #pragma unroll
            for (int j = 0; j < NBANK; j++) {
                const float a = att[r][j] * inv2;
                acc[r][j] = pack2(a, a);
            }
        }

        // ---- GEMM2 + tanh: out[r][:] = tanh(att[r] @ bank), packed f32x2 ------
        float* op = out + row0 * FEA + lane * 4;
        #pragma unroll 1
        for (int cc = 0; cc < NCHUNK; cc++) {
            const int cb = cc * KC + lane * 4;
            u64 olo[RPW], ohi[RPW];
            #pragma unroll
            for (int r = 0; r < RPW; r++) { olo[r] = 0ull; ohi[r] = 0ull; }

            #pragma unroll
            for (int j = 0; j < NBANK; j++) {
                const ulonglong2 b =
                    *reinterpret_cast<const ulonglong2*>(&s_bank[j * FEA + cb]);
                #pragma unroll
                for (int r = 0; r < RPW; r++) {
                    olo[r] = ffma2(acc[r][j], b.x, olo[r]);
                    ohi[r] = ffma2(acc[r][j], b.y, ohi[r]);
                }
            }

            #pragma unroll
            for (int r = 0; r < RPW; r++) {
                float a0, a1, a2, a3;
                unpack2(olo[r], a0, a1);
                unpack2(ohi[r], a2, a3);
                float4 o;
                o.x = tanh_fast(a0);
                o.y = tanh_fast(a1);
                o.z = tanh_fast(a2);
                o.w = tanh_fast(a3);
                *reinterpret_cast<float4*>(op + r * FEA + cc * KC) = o;
            }
        }
    }
}

extern "C" void kernel_launch(void* const* d_in, const int* in_sizes, int n_in,
                              void* d_out, int out_size)
{
    const float* x    = reinterpret_cast<const float*>(d_in[0]);
    const float* bank = reinterpret_cast<const float*>(d_in[1]);
    float* out        = reinterpret_cast<float*>(d_out);

    const int rows    = in_sizes[0] / FEA;   // 32768
    const int n_tiles = rows / RPB;          // 1024

    cudaFuncSetAttribute(memunit_fused,
                         cudaFuncAttributeMaxDynamicSharedMemorySize, SMEM_BYTES);

    int dev = 0, sms = 148;
    cudaGetDevice(&dev);
    cudaDeviceGetAttribute(&sms, cudaDevAttrMultiProcessorCount, dev);

    int grid = (sms < n_tiles) ? sms : n_tiles;
    memunit_fused<<<grid, NTHREADS, SMEM_BYTES>>>(x, bank, out, n_tiles);
}

// round 3
// speedup vs baseline: 1.1306x; 1.1306x over previous
#include <cuda_runtime.h>
#include <cstdint>

// x[32768,2048] fp32, bank[20,2048] fp32 -> out[32768,2048] fp32
constexpr int FEA      = 2048;
constexpr int NBANK    = 20;
constexpr int NJP      = NBANK / 2;       // 10 packed bank-pairs
constexpr int RPW      = 4;               // rows per warp
constexpr int NWARP    = 8;
constexpr int RPB      = RPW * NWARP;     // 32 rows per CTA
constexpr int NTHREADS = 256;
constexpr int KC       = 128;             // k-cols per chunk
constexpr int NCHUNK   = FEA / KC;        // 16
constexpr float LAMBDA = 0.0025f;
constexpr int SMEM_BYTES = NJP * FEA * 8; // 163840 (u64 pairs)

typedef unsigned long long u64;

__device__ __forceinline__ u64 ffma2(u64 a, u64 b, u64 c) {
    u64 d;
    asm("fma.rn.f32x2 %0, %1, %2, %3;" : "=l"(d) : "l"(a), "l"(b), "l"(c));
    return d;
}
__device__ __forceinline__ u64 add2(u64 a, u64 b) {
    u64 d;
    asm("add.rn.f32x2 %0, %1, %2;" : "=l"(d) : "l"(a), "l"(b));
    return d;
}
__device__ __forceinline__ u64 pack2(float lo, float hi) {
    u64 d;
    asm("mov.b64 %0, {%1, %2};" : "=l"(d) : "f"(lo), "f"(hi));
    return d;
}
__device__ __forceinline__ void unpack2(u64 v, float& lo, float& hi) {
    asm("mov.b64 {%0, %1}, %2;" : "=f"(lo), "=f"(hi) : "l"(v));
}
__device__ __forceinline__ float tanh_fast(float v) {
    float r;
    asm("tanh.approx.f32 %0, %1;" : "=f"(r) : "f"(v));
    return r;
}

extern __shared__ u64 s_pair[];   // [NJP][FEA]: (bank[2jp][k], bank[2jp+1][k])

__global__ __launch_bounds__(NTHREADS, 1)
void memunit_fused(const float* __restrict__ x,
                   const float* __restrict__ bank,
                   float* __restrict__ out,
                   int n_tiles)
{
    const int tid = threadIdx.x;

    // Build j-pair-interleaved bank in SMEM once per persistent CTA.
    for (int idx = tid; idx < NJP * FEA; idx += NTHREADS) {
        const int jp = idx >> 11;          // idx / FEA
        const int k  = idx & (FEA - 1);
        s_pair[idx] = pack2(bank[(2 * jp) * FEA + k],
                            bank[(2 * jp + 1) * FEA + k]);
    }
    __syncthreads();

    const int warp = tid >> 5;
    const int lane = tid & 31;
    // Per 128-col chunk, lane owns k = {2i, 2i+1, 64+2i, 65+2i}: conflict-free
    // LDS.128 (16B/lane stride) and coalesced LDG.64/STG.64 (8B/lane stride).
    const int kA = 2 * lane;               // first k-pair offset within chunk
    const int kB = 64 + 2 * lane;          // second k-pair offset

    for (int tile = blockIdx.x; tile < n_tiles; tile += gridDim.x) {
        const long row0 = (long)tile * RPB + warp * RPW;
        const float* xp = x + row0 * FEA;

        // acc[r][jp]: packed (dot(row r, bank[2jp]), dot(row r, bank[2jp+1]))
        u64 acc[RPW][NJP];
        #pragma unroll
        for (int r = 0; r < RPW; r++)
            #pragma unroll
            for (int jp = 0; jp < NJP; jp++) acc[r][jp] = 0ull;

        // prefetch x for chunk 0 (two float2 per row)
        float2 xa[RPW], xb[RPW];
        #pragma unroll
        for (int r = 0; r < RPW; r++) {
            xa[r] = *reinterpret_cast<const float2*>(xp + r * FEA + kA);
            xb[r] = *reinterpret_cast<const float2*>(xp + r * FEA + kB);
        }

        #pragma unroll 1
        for (int kc = 0; kc < NCHUNK; kc++) {
            // broadcast-pack current x values
            u64 pax[RPW], pay[RPW], pbx[RPW], pby[RPW];
            #pragma unroll
            for (int r = 0; r < RPW; r++) {
                pax[r] = pack2(xa[r].x, xa[r].x);
                pay[r] = pack2(xa[r].y, xa[r].y);
                pbx[r] = pack2(xb[r].x, xb[r].x);
                pby[r] = pack2(xb[r].y, xb[r].y);
            }

            // prefetch next chunk (wrap: harmless re-read on last iter)
            const int nk = ((kc + 1) & (NCHUNK - 1)) * KC;
            #pragma unroll
            for (int r = 0; r < RPW; r++) {
                xa[r] = *reinterpret_cast<const float2*>(xp + r * FEA + nk + kA);
                xb[r] = *reinterpret_cast<const float2*>(xp + r * FEA + nk + kB);
            }

            const int cbase = kc * KC;
            #pragma unroll
            for (int jp = 0; jp < NJP; jp++) {
                const u64* bp = s_pair + jp * FEA + cbase;
                const ulonglong2 b0 = *reinterpret_cast<const ulonglong2*>(bp + kA);
                const ulonglong2 b1 = *reinterpret_cast<const ulonglong2*>(bp + kB);
                #pragma unroll
                for (int r = 0; r < RPW; r++) {
                    acc[r][jp] = ffma2(pax[r], b0.x, acc[r][jp]);
                    acc[r][jp] = ffma2(pay[r], b0.y, acc[r][jp]);
                    acc[r][jp] = ffma2(pbx[r], b1.x, acc[r][jp]);
                    acc[r][jp] = ffma2(pby[r], b1.y, acc[r][jp]);
                }
            }
        }

        // ---- butterfly reduce packed pairs across lanes, then softmax chain ---
        u64 ap[RPW][NJP];   // final packed attention (a_{2jp}, a_{2jp+1})
        #pragma unroll
        for (int r = 0; r < RPW; r++) {
            float att[NBANK];
            #pragma unroll
            for (int jp = 0; jp < NJP; jp++) {
                u64 v = acc[r][jp];
                v = add2(v, __shfl_xor_sync(0xffffffffu, v, 16));
                v = add2(v, __shfl_xor_sync(0xffffffffu, v, 8));
                v = add2(v, __shfl_xor_sync(0xffffffffu, v, 4));
                v = add2(v, __shfl_xor_sync(0xffffffffu, v, 2));
                v = add2(v, __shfl_xor_sync(0xffffffffu, v, 1));
                unpack2(v, att[2 * jp], att[2 * jp + 1]);
            }

            float m = att[0];
            #pragma unroll
            for (int j = 1; j < NBANK; j++) m = fmaxf(m, att[j]);

            float s = 0.f;
            #pragma unroll
            for (int j = 0; j < NBANK; j++) {
                const float e = __expf(att[j] - m);
                att[j] = e;
                s += e;
            }
            const float inv = 1.0f / s;

            float m2 = 0.f;   // att >= 0 => softshrink = max(att - lambda, 0)
            #pragma unroll
            for (int j = 0; j < NBANK; j++) {
                const float a = fmaxf(att[j] * inv - LAMBDA, 0.f);
                att[j] = a;
                m2 = fmaxf(m2, a);
            }

            float s2 = 0.f;
            #pragma unroll
            for (int j = 0; j < NBANK; j++) {
                const float e = __expf(att[j] - m2);
                att[j] = e;
                s2 += e;
            }
            const float inv2 = 1.0f / s2;
            #pragma unroll
            for (int jp = 0; jp < NJP; jp++)
                ap[r][jp] = pack2(att[2 * jp] * inv2, att[2 * jp + 1] * inv2);
        }

        // ---- GEMM2 + tanh: out[r][k] = tanh(sum_j att[j] * bank[j][k]) --------
        float* op = out + row0 * FEA;
        #pragma unroll 1
        for (int cc = 0; cc < NCHUNK; cc++) {
            const int cbase = cc * KC;
            u64 o[RPW][4];   // packed partials for lane's 4 k-positions
            #pragma unroll
            for (int r = 0; r < RPW; r++)
                #pragma unroll
                for (int q = 0; q < 4; q++) o[r][q] = 0ull;

            #pragma unroll
            for (int jp = 0; jp < NJP; jp++) {
                const u64* bp = s_pair + jp * FEA + cbase;
                const ulonglong2 b0 = *reinterpret_cast<const ulonglong2*>(bp + kA);
                const ulonglong2 b1 = *reinterpret_cast<const ulonglong2*>(bp + kB);
                #pragma unroll
                for (int r = 0; r < RPW; r++) {
                    o[r][0] = ffma2(ap[r][jp], b0.x, o[r][0]);
                    o[r][1] = ffma2(ap[r][jp], b0.y, o[r][1]);
                    o[r][2] = ffma2(ap[r][jp], b1.x, o[r][2]);
                    o[r][3] = ffma2(ap[r][jp], b1.y, o[r][3]);
                }
            }

            #pragma unroll
            for (int r = 0; r < RPW; r++) {
                float l0, h0, l1, h1, l2, h2, l3, h3;
                unpack2(o[r][0], l0, h0);
                unpack2(o[r][1], l1, h1);
                unpack2(o[r][2], l2, h2);
                unpack2(o[r][3], l3, h3);
                float2 vA, vB;
                vA.x = tanh_fast(l0 + h0);
                vA.y = tanh_fast(l1 + h1);
                vB.x = tanh_fast(l2 + h2);
                vB.y = tanh_fast(l3 + h3);
                *reinterpret_cast<float2*>(op + r * FEA + cbase + kA) = vA;
                *reinterpret_cast<float2*>(op + r * FEA + cbase + kB) = vB;
            }
        }
    }
}

extern "C" void kernel_launch(void* const* d_in, const int* in_sizes, int n_in,
                              void* d_out, int out_size)
{
    const float* x    = reinterpret_cast<const float*>(d_in[0]);
    const float* bank = reinterpret_cast<const float*>(d_in[1]);
    float* out        = reinterpret_cast<float*>(d_out);

    const int rows    = in_sizes[0] / FEA;   // 32768
    const int n_tiles = rows / RPB;          // 1024

    cudaFuncSetAttribute(memunit_fused,
                         cudaFuncAttributeMaxDynamicSharedMemorySize, SMEM_BYTES);

    int dev = 0, sms = 148;
    cudaGetDevice(&dev);
    cudaDeviceGetAttribute(&sms, cudaDevAttrMultiProcessorCount, dev);

    int grid = (sms < n_tiles) ? sms : n_tiles;
    memunit_fused<<<grid, NTHREADS, SMEM_BYTES>>>(x, bank, out, n_tiles);
}

// round 4
// speedup vs baseline: 1.3522x; 1.1960x over previous
#include <cuda_runtime.h>
#include <cstdint>

// x[32768,2048] fp32, bank[20,2048] fp32 -> out[32768,2048] fp32
constexpr int FEA      = 2048;
constexpr int NBANK    = 20;
constexpr int NJP      = NBANK / 2;        // 10 packed bank-pairs
constexpr int RPW      = 4;                // rows per warp
constexpr int NWARP    = 8;
constexpr int RPB      = RPW * NWARP;      // 32 rows per CTA
constexpr int NTHREADS = 256;
constexpr int KC       = 128;              // k-cols per chunk
constexpr int NCHUNK   = FEA / KC;         // 16
constexpr int DEPTH    = 3;                // cp.async ring depth (per warp)
constexpr float LAMBDA = 0.0025f;

constexpr int BANK_U64      = NJP * FEA;           // 20480 u64 = 163840 B
constexpr int XSTAGE_BYTES  = RPW * KC * 4;        // 2048 B per warp-stage
constexpr int XRING_BYTES   = NWARP * DEPTH * XSTAGE_BYTES;   // 49152
constexpr int SMEM_BYTES    = BANK_U64 * 8 + XRING_BYTES;     // 212992

typedef unsigned long long u64;

__device__ __forceinline__ u64 ffma2(u64 a, u64 b, u64 c) {
    u64 d;
    asm("fma.rn.f32x2 %0, %1, %2, %3;" : "=l"(d) : "l"(a), "l"(b), "l"(c));
    return d;
}
__device__ __forceinline__ u64 add2(u64 a, u64 b) {
    u64 d;
    asm("add.rn.f32x2 %0, %1, %2;" : "=l"(d) : "l"(a), "l"(b));
    return d;
}
__device__ __forceinline__ u64 pack2(float lo, float hi) {
    u64 d;
    asm("mov.b64 %0, {%1, %2};" : "=l"(d) : "f"(lo), "f"(hi));
    return d;
}
__device__ __forceinline__ void unpack2(u64 v, float& lo, float& hi) {
    asm("mov.b64 {%0, %1}, %2;" : "=f"(lo), "=f"(hi) : "l"(v));
}
__device__ __forceinline__ float tanh_fast(float v) {
    float r;
    asm("tanh.approx.f32 %0, %1;" : "=f"(r) : "f"(v));
    return r;
}
__device__ __forceinline__ void cp16(uint32_t dst, const float* src) {
    asm volatile("cp.async.cg.shared.global [%0], [%1], 16;\n"
                 :: "r"(dst), "l"(src));
}

extern __shared__ u64 smem_u64[];

__global__ __launch_bounds__(NTHREADS, 1)
void memunit_fused(const float* __restrict__ x,
                   const float* __restrict__ bank,
                   float* __restrict__ out,
                   int n_tiles)
{
    u64*  s_pair = smem_u64;                       // [NJP][FEA], k-swizzled
    char* s_x    = (char*)(smem_u64 + BANK_U64);   // per-warp x ring

    const int tid  = threadIdx.x;
    const int warp = tid >> 5;
    const int lane = tid & 31;
    const int G    = gridDim.x;

    // Build j-pair-interleaved bank with conflict-breaking swizzle:
    // store value for k at index k ^ (((k>>4)&1)<<1)  (swap u64-pairs on bit4).
    for (int idx = tid; idx < BANK_U64; idx += NTHREADS) {
        const int jp = idx >> 11;
        const int k  = idx & (FEA - 1);
        const int ks = k ^ (((k >> 4) & 1) << 1);
        s_pair[jp * FEA + ks] = pack2(bank[(2 * jp) * FEA + k],
                                      bank[(2 * jp + 1) * FEA + k]);
    }
    __syncthreads();

    const int my_tiles = (n_tiles - (int)blockIdx.x + G - 1) / G;
    const uint32_t xs0 =
        (uint32_t)__cvta_generic_to_shared(s_x) +
        (uint32_t)(warp * (DEPTH * XSTAGE_BYTES) + lane * 16);
    const char* xwarp = s_x + warp * (DEPTH * XSTAGE_BYTES);
    const int sw = (lane & 4) ? 2 : 0;             // lane-constant swizzle term

    // ---- issue one chunk (flattened index g) into ring slot ----------------
    auto issue = [&](int g, int slot) {
        const int t2 = g >> 4;                     // which of my tiles
        if (t2 < my_tiles) {
            const int kc2 = g & (NCHUNK - 1);
            const float* src =
                x + ((long)((int)blockIdx.x + t2 * G) * RPB + warp * RPW) * FEA
                  + kc2 * KC + 4 * lane;
            const uint32_t dst = xs0 + slot * XSTAGE_BYTES;
            #pragma unroll
            for (int r = 0; r < RPW; r++)
                cp16(dst + r * 512, src + r * FEA);
        }
        asm volatile("cp.async.commit_group;\n" ::: "memory");
    };

    // prologue: fill the ring
    #pragma unroll
    for (int s = 0; s < DEPTH; s++) issue(s, s);

    int f = 0, slot = 0;

    for (int t = 0; t < my_tiles; t++) {
        const long row0 = (long)((int)blockIdx.x + t * G) * RPB + warp * RPW;

        // ================= GEMM1: acc[r][jp] = packed dots ==================
        u64 acc[RPW][NJP];
        #pragma unroll
        for (int r = 0; r < RPW; r++)
            #pragma unroll
            for (int jp = 0; jp < NJP; jp++) acc[r][jp] = 0ull;

        #pragma unroll 1
        for (int kc = 0; kc < NCHUNK; kc++) {
            asm volatile("cp.async.wait_group 2;\n" ::: "memory");
            __syncwarp();

            const char* xst = xwarp + slot * XSTAGE_BYTES;
            float4 xv[RPW];
            #pragma unroll
            for (int r = 0; r < RPW; r++)
                xv[r] = *reinterpret_cast<const float4*>(xst + r * 512 + lane * 16);

            // refill this slot with chunk f+DEPTH (may cross into next tile)
            issue(f + DEPTH, slot);

            u64 px[RPW][4];
            #pragma unroll
            for (int r = 0; r < RPW; r++) {
                px[r][0] = pack2(xv[r].x, xv[r].x);
                px[r][1] = pack2(xv[r].y, xv[r].y);
                px[r][2] = pack2(xv[r].z, xv[r].z);
                px[r][3] = pack2(xv[r].w, xv[r].w);
            }

            const int i0 = kc * KC + 4 * lane;
            #pragma unroll
            for (int jp = 0; jp < NJP; jp++) {
                const u64* bp = s_pair + jp * FEA;
                const ulonglong2 bA = *reinterpret_cast<const ulonglong2*>(bp + i0 + sw);
                const ulonglong2 bB = *reinterpret_cast<const ulonglong2*>(bp + i0 + 2 - sw);
                #pragma unroll
                for (int r = 0; r < RPW; r++) {
                    acc[r][jp] = ffma2(px[r][0], bA.x, acc[r][jp]);
                    acc[r][jp] = ffma2(px[r][1], bA.y, acc[r][jp]);
                    acc[r][jp] = ffma2(px[r][2], bB.x, acc[r][jp]);
                    acc[r][jp] = ffma2(px[r][3], bB.y, acc[r][jp]);
                }
            }

            f++;
            slot++; if (slot == DEPTH) slot = 0;
        }

        // ====== butterfly-reduce packed pairs, softmax->shrink->softmax =====
        u64 ap[RPW][NJP];
        #pragma unroll
        for (int r = 0; r < RPW; r++) {
            float att[NBANK];
            #pragma unroll
            for (int jp = 0; jp < NJP; jp++) {
                u64 v = acc[r][jp];
                v = add2(v, __shfl_xor_sync(0xffffffffu, v, 16));
                v = add2(v, __shfl_xor_sync(0xffffffffu, v, 8));
                v = add2(v, __shfl_xor_sync(0xffffffffu, v, 4));
                v = add2(v, __shfl_xor_sync(0xffffffffu, v, 2));
                v = add2(v, __shfl_xor_sync(0xffffffffu, v, 1));
                unpack2(v, att[2 * jp], att[2 * jp + 1]);
            }

            float m = att[0];
            #pragma unroll
            for (int j = 1; j < NBANK; j++) m = fmaxf(m, att[j]);

            float s = 0.f;
            #pragma unroll
            for (int j = 0; j < NBANK; j++) {
                const float e = __expf(att[j] - m);
                att[j] = e;
                s += e;
            }
            const float inv = 1.0f / s;

            float m2 = 0.f;   // att >= 0 => softshrink = max(att - lambda, 0)
            #pragma unroll
            for (int j = 0; j < NBANK; j++) {
                const float a = fmaxf(att[j] * inv - LAMBDA, 0.f);
                att[j] = a;
                m2 = fmaxf(m2, a);
            }

            float s2 = 0.f;
            #pragma unroll
            for (int j = 0; j < NBANK; j++) {
                const float e = __expf(att[j] - m2);
                att[j] = e;
                s2 += e;
            }
            const float inv2 = 1.0f / s2;
            #pragma unroll
            for (int jp = 0; jp < NJP; jp++)
                ap[r][jp] = pack2(att[2 * jp] * inv2, att[2 * jp + 1] * inv2);
        }

        // ============= GEMM2 + tanh: out[r][k] = tanh(att . bank[:,k]) ======
        float* op = out + row0 * FEA;
        #pragma unroll 1
        for (int cc = 0; cc < NCHUNK; cc++) {
            const int i0 = cc * KC + 4 * lane;
            u64 o[RPW][4];
            #pragma unroll
            for (int r = 0; r < RPW; r++)
                #pragma unroll
                for (int q = 0; q < 4; q++) o[r][q] = 0ull;

            #pragma unroll
            for (int jp = 0; jp < NJP; jp++) {
                const u64* bp = s_pair + jp * FEA;
                const ulonglong2 bA = *reinterpret_cast<const ulonglong2*>(bp + i0 + sw);
                const ulonglong2 bB = *reinterpret_cast<const ulonglong2*>(bp + i0 + 2 - sw);
                #pragma unroll
                for (int r = 0; r < RPW; r++) {
                    o[r][0] = ffma2(ap[r][jp], bA.x, o[r][0]);
                    o[r][1] = ffma2(ap[r][jp], bA.y, o[r][1]);
                    o[r][2] = ffma2(ap[r][jp], bB.x, o[r][2]);
                    o[r][3] = ffma2(ap[r][jp], bB.y, o[r][3]);
                }
            }

            #pragma unroll
            for (int r = 0; r < RPW; r++) {
                float l0, h0, l1, h1, l2, h2, l3, h3;
                unpack2(o[r][0], l0, h0);
                unpack2(o[r][1], l1, h1);
                unpack2(o[r][2], l2, h2);
                unpack2(o[r][3], l3, h3);
                float4 v;
                v.x = tanh_fast(l0 + h0);
                v.y = tanh_fast(l1 + h1);
                v.z = tanh_fast(l2 + h2);
                v.w = tanh_fast(l3 + h3);
                *reinterpret_cast<float4*>(op + r * FEA + cc * KC + 4 * lane) = v;
            }
        }
    }
}

extern "C" void kernel_launch(void* const* d_in, const int* in_sizes, int n_in,
                              void* d_out, int out_size)
{
    const float* x    = reinterpret_cast<const float*>(d_in[0]);
    const float* bank = reinterpret_cast<const float*>(d_in[1]);
    float* out        = reinterpret_cast<float*>(d_out);

    const int rows    = in_sizes[0] / FEA;   // 32768
    const int n_tiles = rows / RPB;          // 1024

    cudaFuncSetAttribute(memunit_fused,
                         cudaFuncAttributeMaxDynamicSharedMemorySize, SMEM_BYTES);

    int dev = 0, sms = 148;
    cudaGetDevice(&dev);
    cudaDeviceGetAttribute(&sms, cudaDevAttrMultiProcessorCount, dev);

    int grid = (sms < n_tiles) ? sms : n_tiles;
    memunit_fused<<<grid, NTHREADS, SMEM_BYTES>>>(x, bank, out, n_tiles);
}